// round 1
// baseline (speedup 1.0000x reference)
#include <cuda_runtime.h>

#define NN     10000
#define EE     30000
#define FEDGE  8
#define EMB    64
#define HID    16
#define NG     64
#define NCOL   1088   // HID*EMB (P part) + EMB (Q part)

// ---------------- scratch (device globals; no allocation) ----------------
__device__ float g_h0[EE * HID];
__device__ float g_h1[EE * HID];
__device__ float g_PQ[NN * NCOL];       // per-node [16x64 P | 64 Q]
__device__ float g_x[NN * EMB];
__device__ float g_agg[NN * EMB];
__device__ float g_Wr[EMB * NCOL];      // reordered w2||b2, rows = input dim (<=64)
__device__ float g_pool[NG * EMB];

// ---------------- edge MLP hidden layers (both convs' MLPs at once) ------
__global__ __launch_bounds__(128) void edge_hidden_kernel(
    const float* __restrict__ ea,
    const float* __restrict__ w10, const float* __restrict__ b10,
    const float* __restrict__ w11, const float* __restrict__ b11)
{
    __shared__ float sw0[FEDGE * HID], sw1[FEDGE * HID];
    __shared__ float sb0[HID], sb1[HID];
    int tid = threadIdx.x;
    if (tid < FEDGE * HID) { sw0[tid] = w10[tid]; sw1[tid] = w11[tid]; }
    if (tid < HID)         { sb0[tid] = b10[tid]; sb1[tid] = b11[tid]; }
    __syncthreads();

    int e = blockIdx.x * 128 + tid;
    if (e >= EE) return;

    const float4* p = reinterpret_cast<const float4*>(ea + (size_t)e * FEDGE);
    float4 v0 = p[0], v1 = p[1];
    float a[8] = {v0.x, v0.y, v0.z, v0.w, v1.x, v1.y, v1.z, v1.w};

#pragma unroll
    for (int h = 0; h < HID; h++) {
        float s0 = sb0[h], s1 = sb1[h];
#pragma unroll
        for (int j = 0; j < FEDGE; j++) {
            s0 += a[j] * sw0[j * HID + h];
            s1 += a[j] * sw1[j * HID + h];
        }
        g_h0[e * HID + h] = fmaxf(s0, 0.f);
        g_h1[e * HID + h] = fmaxf(s1, 0.f);
    }
}

// ---------------- reorder w2 (HID, D*64) + b2 (D*64) -> Wr[D][1088] ------
__global__ __launch_bounds__(256) void reorder_w_kernel(
    const float* __restrict__ w2, const float* __restrict__ b2, int D)
{
    int idx = blockIdx.x * 256 + threadIdx.x;
    if (idx >= D * NCOL) return;
    int i = idx / NCOL, c = idx % NCOL;
    float v;
    if (c < HID * EMB) {
        int h = c >> 6, o = c & 63;
        v = w2[(size_t)h * (D * EMB) + i * EMB + o];
    } else {
        v = b2[i * EMB + (c - HID * EMB)];
    }
    g_Wr[i * NCOL + c] = v;
}

// ---------------- node precompute GEMM: PQ[n,:] = x[n,:D] @ Wr -----------
// BM=128, BN=64, K=D (one smem stage). 256 thr, 8x4 register tile each.
template <int D, bool USE_GX>
__global__ __launch_bounds__(256) void node_gemm_kernel(const float* __restrict__ xin)
{
    const int BM = 128, BN = 64;
    __shared__ float As[D][BM];       // [k][row]
    __shared__ float Bs[D][BN];       // [k][col]

    const float* __restrict__ xp = USE_GX ? g_x : xin;
    int tid = threadIdx.x;
    int m0 = blockIdx.y * BM;
    int c0 = blockIdx.x * BN;

    // A: lanes map row-fastest -> conflict-free smem stores (global is
    // sector-granular anyway; x is L2-resident).
#pragma unroll
    for (int t = tid; t < BM * (D / 4); t += 256) {
        int r  = t & (BM - 1);
        int kq = t >> 7;               // t / 128
        int n  = m0 + r;
        float4 v = make_float4(0.f, 0.f, 0.f, 0.f);
        if (n < NN) v = *reinterpret_cast<const float4*>(xp + (size_t)n * D + kq * 4);
        As[kq * 4 + 0][r] = v.x;
        As[kq * 4 + 1][r] = v.y;
        As[kq * 4 + 2][r] = v.z;
        As[kq * 4 + 3][r] = v.w;
    }
    // B: coalesced rows of Wr
#pragma unroll
    for (int t = tid; t < BN * (D / 4); t += 256) {
        int k  = t / (BN / 4);
        int cq = t % (BN / 4);
        float4 v = *reinterpret_cast<const float4*>(g_Wr + (size_t)k * NCOL + c0 + cq * 4);
        *reinterpret_cast<float4*>(&Bs[k][cq * 4]) = v;
    }
    __syncthreads();

    int tx = tid & 15;                 // 16 col groups of 4
    int ty = tid >> 4;                 // 16 row groups of 8
    float acc[8][4];
#pragma unroll
    for (int r = 0; r < 8; r++)
#pragma unroll
        for (int c = 0; c < 4; c++) acc[r][c] = 0.f;

#pragma unroll
    for (int k = 0; k < D; k++) {
        float4 b  = *reinterpret_cast<const float4*>(&Bs[k][tx * 4]);
        float4 a0 = *reinterpret_cast<const float4*>(&As[k][ty * 8]);
        float4 a1 = *reinterpret_cast<const float4*>(&As[k][ty * 8 + 4]);
        float av[8] = {a0.x, a0.y, a0.z, a0.w, a1.x, a1.y, a1.z, a1.w};
        float bv[4] = {b.x, b.y, b.z, b.w};
#pragma unroll
        for (int r = 0; r < 8; r++)
#pragma unroll
            for (int c = 0; c < 4; c++) acc[r][c] += av[r] * bv[c];
    }

#pragma unroll
    for (int r = 0; r < 8; r++) {
        int n = m0 + ty * 8 + r;
        if (n < NN) {
            *reinterpret_cast<float4*>(g_PQ + (size_t)n * NCOL + c0 + tx * 4) =
                make_float4(acc[r][0], acc[r][1], acc[r][2], acc[r][3]);
        }
    }
}

// ---------------- per-edge message + scatter-add -------------------------
// one warp per edge: msg[o] = Q[src,o] + sum_h h[e,h]*P[src,h,o]
__global__ __launch_bounds__(256) void edge_msg_kernel(const int* __restrict__ ei, int which)
{
    int warp = (blockIdx.x * 256 + threadIdx.x) >> 5;
    int lane = threadIdx.x & 31;
    if (warp >= EE) return;

    const float* __restrict__ hsrc = which ? g_h1 : g_h0;
    int src = ei[warp];
    int dst = ei[EE + warp];

    float hv = (lane < HID) ? hsrc[(size_t)warp * HID + lane] : 0.f;
    const float* __restrict__ P = g_PQ + (size_t)src * NCOL;

    float acc0 = P[HID * EMB + lane];
    float acc1 = P[HID * EMB + 32 + lane];
#pragma unroll
    for (int h = 0; h < HID; h++) {
        float w = __shfl_sync(0xffffffffu, hv, h);
        acc0 += w * P[h * EMB + lane];
        acc1 += w * P[h * EMB + 32 + lane];
    }
    atomicAdd(g_agg + (size_t)dst * EMB + lane, acc0);
    atomicAdd(g_agg + (size_t)dst * EMB + 32 + lane, acc1);
}

// ---------------- combine: x_new = relu(agg + x @ root + bias) -----------
template <int D, bool USE_GX>
__global__ __launch_bounds__(256) void combine_kernel(
    const float* __restrict__ xin, const float* __restrict__ root,
    const float* __restrict__ bias)
{
    __shared__ float rs[D * EMB];
    __shared__ float xs[4][D];
    const float* __restrict__ xp = USE_GX ? g_x : xin;

    int tid = threadIdx.x;
#pragma unroll
    for (int t = tid; t < D * EMB / 4; t += 256)
        reinterpret_cast<float4*>(rs)[t] = reinterpret_cast<const float4*>(root)[t];
    for (int t = tid; t < 4 * D; t += 256) {
        int l = t / D, i = t % D;
        int n2 = blockIdx.x * 4 + l;
        xs[l][i] = (n2 < NN) ? xp[(size_t)n2 * D + i] : 0.f;
    }
    __syncthreads();

    int l = tid >> 6, o = tid & 63;
    int n = blockIdx.x * 4 + l;
    if (n >= NN) return;

    float acc = g_agg[(size_t)n * EMB + o] + bias[o];
#pragma unroll
    for (int i = 0; i < D; i++) acc += xs[l][i] * rs[i * EMB + o];
    g_x[(size_t)n * EMB + o] = fmaxf(acc, 0.f);
}

// ---------------- zero scratch --------------------------------------------
__global__ __launch_bounds__(256) void zero_agg_kernel()
{
    int i = blockIdx.x * 256 + threadIdx.x;
    if (i < NN * EMB) g_agg[i] = 0.f;
}
__global__ __launch_bounds__(256) void zero_pool_kernel()
{
    int i = blockIdx.x * 256 + threadIdx.x;
    if (i < NG * EMB) g_pool[i] = 0.f;
}

// ---------------- segment max pool (batch ids sorted, x >= 0) -------------
__global__ __launch_bounds__(256) void pool_kernel(const int* __restrict__ batch)
{
    int tid = threadIdx.x;
    int o = tid & 63, seg = tid >> 6;
    int n0 = blockIdx.x * 32 + seg * 8;
    int curb = -1;
    float m = 0.f;
    for (int k = 0; k < 8; k++) {
        int n = n0 + k;
        if (n >= NN) break;
        int b = batch[n];
        if (b != curb) {
            if (curb >= 0)
                atomicMax(reinterpret_cast<unsigned*>(g_pool + (size_t)curb * EMB + o),
                          __float_as_uint(m));
            curb = b;
            m = 0.f;
        }
        m = fmaxf(m, g_x[(size_t)n * EMB + o]);
    }
    if (curb >= 0)
        atomicMax(reinterpret_cast<unsigned*>(g_pool + (size_t)curb * EMB + o),
                  __float_as_uint(m));
}

// ---------------- head: out[g] = (pooled@lin0 + b0) @ lin1 + b1 ----------
__global__ __launch_bounds__(64) void head_kernel(
    const float* __restrict__ lin0w, const float* __restrict__ lin0b,
    const float* __restrict__ lin1w, const float* __restrict__ lin1b,
    float* __restrict__ out)
{
    __shared__ float pg[EMB];
    __shared__ float red[EMB];
    int g = blockIdx.x, o = threadIdx.x;
    pg[o] = g_pool[(size_t)g * EMB + o];
    __syncthreads();

    float h = lin0b[o];
#pragma unroll
    for (int i = 0; i < EMB; i++) h += pg[i] * lin0w[i * EMB + o];
    red[o] = h * lin1w[o];
    __syncthreads();
#pragma unroll
    for (int s = 32; s > 0; s >>= 1) {
        if (o < s) red[o] += red[o + s];
        __syncthreads();
    }
    if (o == 0) out[g] = red[0] + lin1b[0];
}

// ---------------- launch ---------------------------------------------------
extern "C" void kernel_launch(void* const* d_in, const int* in_sizes, int n_in,
                              void* d_out, int out_size)
{
    const float* x_p    = (const float*)d_in[0];
    // d_in[1]: x_d (unused by reference math)
    const float* ea     = (const float*)d_in[2];
    // d_in[3]: edge_attr_d (unused)
    const int*   ei     = (const int*)  d_in[4];
    const int*   batch  = (const int*)  d_in[5];
    const float* nn0_w1 = (const float*)d_in[6];
    const float* nn0_b1 = (const float*)d_in[7];
    const float* nn0_w2 = (const float*)d_in[8];
    const float* nn0_b2 = (const float*)d_in[9];
    const float* nn1_w1 = (const float*)d_in[10];
    const float* nn1_b1 = (const float*)d_in[11];
    const float* nn1_w2 = (const float*)d_in[12];
    const float* nn1_b2 = (const float*)d_in[13];
    const float* root0  = (const float*)d_in[14];
    const float* bias0  = (const float*)d_in[15];
    const float* root1  = (const float*)d_in[16];
    const float* bias1  = (const float*)d_in[17];
    const float* root2  = (const float*)d_in[18];
    const float* bias2  = (const float*)d_in[19];
    const float* lin0_w = (const float*)d_in[20];
    const float* lin0_b = (const float*)d_in[21];
    const float* lin1_w = (const float*)d_in[22];
    const float* lin1_b = (const float*)d_in[23];
    float* out = (float*)d_out;

    dim3 gemm_grid(NCOL / 64, (NN + 127) / 128);
    int zero_blocks = (NN * EMB + 255) / 256;
    int msg_blocks  = (EE + 7) / 8;

    // edge MLP hiddens (shared by all convs)
    edge_hidden_kernel<<<(EE + 127) / 128, 128>>>(ea, nn0_w1, nn0_b1, nn1_w1, nn1_b1);

    // ---- conv0 (input dim 32) ----
    reorder_w_kernel<<<(32 * NCOL + 255) / 256, 256>>>(nn0_w2, nn0_b2, 32);
    node_gemm_kernel<32, false><<<gemm_grid, 256>>>(x_p);
    zero_agg_kernel<<<zero_blocks, 256>>>();
    edge_msg_kernel<<<msg_blocks, 256>>>(ei, 0);
    combine_kernel<32, false><<<(NN + 3) / 4, 256>>>(x_p, root0, bias0);

    // ---- convs 1 & 2 (input dim 64, shared edge MLP) ----
    reorder_w_kernel<<<(64 * NCOL + 255) / 256, 256>>>(nn1_w2, nn1_b2, 64);

    node_gemm_kernel<64, true><<<gemm_grid, 256>>>(nullptr);
    zero_agg_kernel<<<zero_blocks, 256>>>();
    edge_msg_kernel<<<msg_blocks, 256>>>(ei, 1);
    combine_kernel<64, true><<<(NN + 3) / 4, 256>>>(nullptr, root1, bias1);

    node_gemm_kernel<64, true><<<gemm_grid, 256>>>(nullptr);
    zero_agg_kernel<<<zero_blocks, 256>>>();
    edge_msg_kernel<<<msg_blocks, 256>>>(ei, 1);
    combine_kernel<64, true><<<(NN + 3) / 4, 256>>>(nullptr, root2, bias2);

    // ---- pool + head ----
    zero_pool_kernel<<<(NG * EMB + 255) / 256, 256>>>();
    pool_kernel<<<(NN + 31) / 32, 256>>>(batch);
    head_kernel<<<NG, 64>>>(lin0_w, lin0_b, lin1_w, lin1_b, out);
}